// round 1
// baseline (speedup 1.0000x reference)
#include <cuda_runtime.h>
#include <cstdint>

#define MAX_ATOMS 50000
#define DD 256
#define NB 16

// Scratch for h = x @ W.T + b (row 0 zeroed). 51.2 MB device global (no allocs allowed).
__device__ float g_h[(size_t)MAX_ATOMS * DD];

// ---------------------------------------------------------------------------
// tf32 helpers
// ---------------------------------------------------------------------------
__device__ __forceinline__ uint32_t f2tf32(float f) {
    uint32_t u;
    asm("cvt.rna.tf32.f32 %0, %1;" : "=r"(u) : "f"(f));
    return u;
}

__device__ __forceinline__ void mma_tf32(float d[4], const uint32_t a[4],
                                         const uint32_t b[2], const float c[4]) {
    asm volatile(
        "mma.sync.aligned.m16n8k8.row.col.f32.tf32.tf32.f32 "
        "{%0,%1,%2,%3}, {%4,%5,%6,%7}, {%8,%9}, {%10,%11,%12,%13};"
        : "=f"(d[0]), "=f"(d[1]), "=f"(d[2]), "=f"(d[3])
        : "r"(a[0]), "r"(a[1]), "r"(a[2]), "r"(a[3]),
          "r"(b[0]), "r"(b[1]),
          "f"(c[0]), "f"(c[1]), "f"(c[2]), "f"(c[3]));
}

// ---------------------------------------------------------------------------
// Kernel 1: h[m][n] = sum_k x[m][k] * W[n][k] + b[n];  h[0][:] = 0
// Block: 128 threads (4 warps, 2x2), tile 64(M) x 64(N), K-chunks of 32.
// ---------------------------------------------------------------------------
__global__ __launch_bounds__(128) void gemm_kernel(
    const float* __restrict__ x, const float* __restrict__ W,
    const float* __restrict__ bias, int M)
{
    __shared__ uint32_t As[64][33];   // [row][k], padded stride 33
    __shared__ uint32_t Bs[64][33];   // [n][k],  padded stride 33

    const int tid  = threadIdx.x;
    const int bm   = blockIdx.x * 64;
    const int bn   = blockIdx.y * 64;
    const int warp = tid >> 5;
    const int lane = tid & 31;
    const int wr   = (warp >> 1) * 32;   // warp row offset within tile
    const int wc   = (warp & 1) * 32;    // warp col offset within tile
    const int g    = lane >> 2;          // group id 0..7
    const int tg   = lane & 3;           // thread-in-group 0..3

    float acc[2][4][4];
    #pragma unroll
    for (int mi = 0; mi < 2; mi++)
        #pragma unroll
        for (int ni = 0; ni < 4; ni++)
            #pragma unroll
            for (int e = 0; e < 4; e++) acc[mi][ni][e] = 0.f;

    const int ar = tid >> 3;          // 0..15
    const int ac = (tid & 7) * 4;     // 0,4,...,28

    for (int k0 = 0; k0 < DD; k0 += 32) {
        #pragma unroll
        for (int p = 0; p < 4; p++) {
            const int row  = ar + p * 16;
            const int grow = bm + row;
            float4 va = (grow < M)
                ? *(const float4*)(x + (size_t)grow * DD + k0 + ac)
                : make_float4(0.f, 0.f, 0.f, 0.f);
            As[row][ac + 0] = f2tf32(va.x);
            As[row][ac + 1] = f2tf32(va.y);
            As[row][ac + 2] = f2tf32(va.z);
            As[row][ac + 3] = f2tf32(va.w);
            float4 vb = *(const float4*)(W + (size_t)(bn + row) * DD + k0 + ac);
            Bs[row][ac + 0] = f2tf32(vb.x);
            Bs[row][ac + 1] = f2tf32(vb.y);
            Bs[row][ac + 2] = f2tf32(vb.z);
            Bs[row][ac + 3] = f2tf32(vb.w);
        }
        __syncthreads();

        #pragma unroll
        for (int kk = 0; kk < 32; kk += 8) {
            uint32_t afr[2][4];
            uint32_t bfr[4][2];
            #pragma unroll
            for (int mi = 0; mi < 2; mi++) {
                const int r0 = wr + mi * 16 + g;
                afr[mi][0] = As[r0    ][kk + tg];
                afr[mi][1] = As[r0 + 8][kk + tg];
                afr[mi][2] = As[r0    ][kk + tg + 4];
                afr[mi][3] = As[r0 + 8][kk + tg + 4];
            }
            #pragma unroll
            for (int ni = 0; ni < 4; ni++) {
                const int n0 = wc + ni * 8 + g;
                bfr[ni][0] = Bs[n0][kk + tg];
                bfr[ni][1] = Bs[n0][kk + tg + 4];
            }
            #pragma unroll
            for (int mi = 0; mi < 2; mi++)
                #pragma unroll
                for (int ni = 0; ni < 4; ni++)
                    mma_tf32(acc[mi][ni], afr[mi], bfr[ni], acc[mi][ni]);
        }
        __syncthreads();
    }

    // Epilogue: add bias, zero row 0, store to g_h.
    #pragma unroll
    for (int mi = 0; mi < 2; mi++) {
        #pragma unroll
        for (int ni = 0; ni < 4; ni++) {
            const int col = bn + wc + ni * 8 + tg * 2;
            const float b0 = bias[col];
            const float b1 = bias[col + 1];
            const int r0 = bm + wr + mi * 16 + g;
            const int r1 = r0 + 8;
            if (r0 < M) {
                const float v0 = (r0 == 0) ? 0.f : acc[mi][ni][0] + b0;
                const float v1 = (r0 == 0) ? 0.f : acc[mi][ni][1] + b1;
                g_h[(size_t)r0 * DD + col]     = v0;
                g_h[(size_t)r0 * DD + col + 1] = v1;
            }
            if (r1 < M) {   // r1 >= 8, never the padding row
                g_h[(size_t)r1 * DD + col]     = acc[mi][ni][2] + b0;
                g_h[(size_t)r1 * DD + col + 1] = acc[mi][ni][3] + b1;
            }
        }
    }
}

// ---------------------------------------------------------------------------
// Kernel 2: out[i] = relu(h[i] + sum_k h[b_from_a[a_from_b[i][k]]])
// 256 threads/block = 4 atoms; each atom handled by 64 lanes, float4 per lane.
// All 16 gather loads issued independently (unrolled) for MLP.
// ---------------------------------------------------------------------------
__global__ __launch_bounds__(256) void agg_kernel(
    const int* __restrict__ b_from_a, const int* __restrict__ a_from_b,
    float* __restrict__ out, int M)
{
    const int atom = blockIdx.x * 4 + (threadIdx.x >> 6);
    if (atom >= M) return;
    const int t = threadIdx.x & 63;

    int idx[NB];
    #pragma unroll
    for (int k = 0; k < NB; k++) idx[k] = __ldg(a_from_b + (size_t)atom * NB + k);
    #pragma unroll
    for (int k = 0; k < NB; k++) idx[k] = __ldg(b_from_a + idx[k]);

    const float4* h4 = (const float4*)g_h;
    float4 acc = h4[(size_t)atom * (DD / 4) + t];

    #pragma unroll
    for (int k = 0; k < NB; k++) {
        float4 v = __ldg(h4 + (size_t)idx[k] * (DD / 4) + t);
        acc.x += v.x; acc.y += v.y; acc.z += v.z; acc.w += v.w;
    }

    acc.x = fmaxf(acc.x, 0.f);
    acc.y = fmaxf(acc.y, 0.f);
    acc.z = fmaxf(acc.z, 0.f);
    acc.w = fmaxf(acc.w, 0.f);
    ((float4*)out)[(size_t)atom * (DD / 4) + t] = acc;
}

// ---------------------------------------------------------------------------
// Launch: inputs per metadata order: x, W, b, b_from_a, a_from_b
// ---------------------------------------------------------------------------
extern "C" void kernel_launch(void* const* d_in, const int* in_sizes, int n_in,
                              void* d_out, int out_size) {
    const float* x        = (const float*)d_in[0];
    const float* W        = (const float*)d_in[1];
    const float* bias     = (const float*)d_in[2];
    const int*   b_from_a = (const int*)d_in[3];
    const int*   a_from_b = (const int*)d_in[4];
    float*       out      = (float*)d_out;

    const int M = in_sizes[0] / DD;   // 50000

    dim3 ggrid((M + 63) / 64, DD / 64);
    gemm_kernel<<<ggrid, 128>>>(x, W, bias, M);

    const int ablocks = (M + 3) / 4;
    agg_kernel<<<ablocks, 256>>>(b_from_a, a_from_b, out, M);
}

// round 3
// speedup vs baseline: 1.3621x; 1.3621x over previous
#include <cuda_runtime.h>
#include <cstdint>

#define MAX_ATOMS 50000
#define DD 256
#define NB 16

#define BM 128
#define BN 64
#define BK 16
#define NCHUNK (DD / BK)   // 16
#define SSTRIDE 20         // 16 + 4 pad; %4==0 for v4, conflict-free frag LDS

// Scratch for h = x @ W.T + b (row 0 zeroed). 51.2 MB device global.
__device__ float g_h[(size_t)MAX_ATOMS * DD];

// ---------------------------------------------------------------------------
// tf32 helpers
// ---------------------------------------------------------------------------
__device__ __forceinline__ uint32_t f2tf32(float f) {
    uint32_t u;
    asm("cvt.rna.tf32.f32 %0, %1;" : "=r"(u) : "f"(f));
    return u;
}

__device__ __forceinline__ void mma_tf32(float d[4], const uint32_t a[4],
                                         const uint32_t b[2], const float c[4]) {
    asm volatile(
        "mma.sync.aligned.m16n8k8.row.col.f32.tf32.tf32.f32 "
        "{%0,%1,%2,%3}, {%4,%5,%6,%7}, {%8,%9}, {%10,%11,%12,%13};"
        : "=f"(d[0]), "=f"(d[1]), "=f"(d[2]), "=f"(d[3])
        : "r"(a[0]), "r"(a[1]), "r"(a[2]), "r"(a[3]),
          "r"(b[0]), "r"(b[1]),
          "f"(c[0]), "f"(c[1]), "f"(c[2]), "f"(c[3]));
}

// ---------------------------------------------------------------------------
// Kernel 1: h = x @ W.T + b, row 0 zeroed.
// 256 threads = 8 warps (4x2), block tile 128x64, warp tile 32x32.
// Double-buffered smem, register prefetch 1 chunk ahead of STS.
// ---------------------------------------------------------------------------
__global__ __launch_bounds__(256) void gemm_kernel(
    const float* __restrict__ x, const float* __restrict__ W,
    const float* __restrict__ bias, int M)
{
    __shared__ uint32_t As[2][BM][SSTRIDE];
    __shared__ uint32_t Bs[2][BN][SSTRIDE];

    const int tid  = threadIdx.x;
    const int bn   = blockIdx.x * BN;   // N tiles on x (adjacent blocks share x rows)
    const int bm   = blockIdx.y * BM;
    const int warp = tid >> 5;
    const int lane = tid & 31;
    const int wr   = (warp >> 1) * 32;  // warp row in tile (0,32,64,96)
    const int wc   = (warp & 1) * 32;   // warp col in tile (0,32)
    const int g    = lane >> 2;
    const int tg   = lane & 3;

    // Global-load coords: A gets 2 float4/thread, B gets 1 float4/thread per chunk.
    const int arow = tid >> 2;          // 0..63 (and +64)
    const int acol = (tid & 3) * 4;     // 0,4,8,12
    const int grow0 = bm + arow;
    const int grow1 = bm + arow + 64;
    const float* xp0 = x + (size_t)grow0 * DD + acol;
    const float* xp1 = x + (size_t)grow1 * DD + acol;
    const float* wp  = W + (size_t)(bn + arow) * DD + acol;
    const bool v0 = grow0 < M;
    const bool v1 = grow1 < M;

    float acc[2][4][4];
    #pragma unroll
    for (int mi = 0; mi < 2; mi++)
        #pragma unroll
        for (int ni = 0; ni < 4; ni++)
            #pragma unroll
            for (int e = 0; e < 4; e++) acc[mi][ni][e] = 0.f;

    const float4 z4 = make_float4(0.f, 0.f, 0.f, 0.f);
    float4 pa0, pa1, pb;

    // ---- prologue: chunk 0 -> buf 0
    pa0 = v0 ? *(const float4*)(xp0) : z4;
    pa1 = v1 ? *(const float4*)(xp1) : z4;
    pb  = *(const float4*)(wp);
    {
        uint4 u;
        u.x = f2tf32(pa0.x); u.y = f2tf32(pa0.y); u.z = f2tf32(pa0.z); u.w = f2tf32(pa0.w);
        *(uint4*)&As[0][arow][acol] = u;
        u.x = f2tf32(pa1.x); u.y = f2tf32(pa1.y); u.z = f2tf32(pa1.z); u.w = f2tf32(pa1.w);
        *(uint4*)&As[0][arow + 64][acol] = u;
        u.x = f2tf32(pb.x);  u.y = f2tf32(pb.y);  u.z = f2tf32(pb.z);  u.w = f2tf32(pb.w);
        *(uint4*)&Bs[0][arow][acol] = u;
    }
    __syncthreads();

    // ---- prefetch chunk 1 into regs
    pa0 = v0 ? *(const float4*)(xp0 + BK) : z4;
    pa1 = v1 ? *(const float4*)(xp1 + BK) : z4;
    pb  = *(const float4*)(wp + BK);

    #pragma unroll 1
    for (int c = 0; c < NCHUNK; c++) {
        const int cur = c & 1;

        // compute chunk c from smem
        #pragma unroll
        for (int kk = 0; kk < BK; kk += 8) {
            uint32_t afr[2][4];
            uint32_t bfr[4][2];
            #pragma unroll
            for (int mi = 0; mi < 2; mi++) {
                const int r0 = wr + mi * 16 + g;
                afr[mi][0] = As[cur][r0    ][kk + tg];
                afr[mi][1] = As[cur][r0 + 8][kk + tg];
                afr[mi][2] = As[cur][r0    ][kk + tg + 4];
                afr[mi][3] = As[cur][r0 + 8][kk + tg + 4];
            }
            #pragma unroll
            for (int ni = 0; ni < 4; ni++) {
                const int n0 = wc + ni * 8 + g;
                bfr[ni][0] = Bs[cur][n0][kk + tg];
                bfr[ni][1] = Bs[cur][n0][kk + tg + 4];
            }
            #pragma unroll
            for (int mi = 0; mi < 2; mi++)
                #pragma unroll
                for (int ni = 0; ni < 4; ni++)
                    mma_tf32(acc[mi][ni], afr[mi], bfr[ni], acc[mi][ni]);
        }

        if (c < NCHUNK - 1) {
            // store prefetched chunk c+1 into the other buffer
            const int nxt = cur ^ 1;
            uint4 u;
            u.x = f2tf32(pa0.x); u.y = f2tf32(pa0.y); u.z = f2tf32(pa0.z); u.w = f2tf32(pa0.w);
            *(uint4*)&As[nxt][arow][acol] = u;
            u.x = f2tf32(pa1.x); u.y = f2tf32(pa1.y); u.z = f2tf32(pa1.z); u.w = f2tf32(pa1.w);
            *(uint4*)&As[nxt][arow + 64][acol] = u;
            u.x = f2tf32(pb.x);  u.y = f2tf32(pb.y);  u.z = f2tf32(pb.z);  u.w = f2tf32(pb.w);
            *(uint4*)&Bs[nxt][arow][acol] = u;
            __syncthreads();

            // prefetch chunk c+2 (covered by compute of chunk c+1)
            if (c < NCHUNK - 2) {
                const int ko = (c + 2) * BK;
                pa0 = v0 ? *(const float4*)(xp0 + ko) : z4;
                pa1 = v1 ? *(const float4*)(xp1 + ko) : z4;
                pb  = *(const float4*)(wp + ko);
            }
        }
    }

    // ---- epilogue: add bias, zero row 0, store to g_h
    #pragma unroll
    for (int mi = 0; mi < 2; mi++) {
        #pragma unroll
        for (int ni = 0; ni < 4; ni++) {
            const int col = bn + wc + ni * 8 + tg * 2;
            const float b0 = bias[col];
            const float b1 = bias[col + 1];
            const int r0 = bm + wr + mi * 16 + g;
            const int r1 = r0 + 8;
            if (r0 < M) {
                const float s0 = (r0 == 0) ? 0.f : acc[mi][ni][0] + b0;
                const float s1 = (r0 == 0) ? 0.f : acc[mi][ni][1] + b1;
                g_h[(size_t)r0 * DD + col]     = s0;
                g_h[(size_t)r0 * DD + col + 1] = s1;
            }
            if (r1 < M) {
                g_h[(size_t)r1 * DD + col]     = acc[mi][ni][2] + b0;
                g_h[(size_t)r1 * DD + col + 1] = acc[mi][ni][3] + b1;
            }
        }
    }
}

// ---------------------------------------------------------------------------
// Kernel 2: out[i] = relu(h[i] + sum_k h[b_from_a[a_from_b[i][k]]])
// (unchanged — measured at its L2-bound floor)
// ---------------------------------------------------------------------------
__global__ __launch_bounds__(256) void agg_kernel(
    const int* __restrict__ b_from_a, const int* __restrict__ a_from_b,
    float* __restrict__ out, int M)
{
    const int atom = blockIdx.x * 4 + (threadIdx.x >> 6);
    if (atom >= M) return;
    const int t = threadIdx.x & 63;

    int idx[NB];
    #pragma unroll
    for (int k = 0; k < NB; k++) idx[k] = __ldg(a_from_b + (size_t)atom * NB + k);
    #pragma unroll
    for (int k = 0; k < NB; k++) idx[k] = __ldg(b_from_a + idx[k]);

    const float4* h4 = (const float4*)g_h;
    float4 acc = h4[(size_t)atom * (DD / 4) + t];

    #pragma unroll
    for (int k = 0; k < NB; k++) {
        float4 v = __ldg(h4 + (size_t)idx[k] * (DD / 4) + t);
        acc.x += v.x; acc.y += v.y; acc.z += v.z; acc.w += v.w;
    }

    acc.x = fmaxf(acc.x, 0.f);
    acc.y = fmaxf(acc.y, 0.f);
    acc.z = fmaxf(acc.z, 0.f);
    acc.w = fmaxf(acc.w, 0.f);
    ((float4*)out)[(size_t)atom * (DD / 4) + t] = acc;
}

// ---------------------------------------------------------------------------
// Launch: inputs per metadata order: x, W, b, b_from_a, a_from_b
// ---------------------------------------------------------------------------
extern "C" void kernel_launch(void* const* d_in, const int* in_sizes, int n_in,
                              void* d_out, int out_size) {
    const float* x        = (const float*)d_in[0];
    const float* W        = (const float*)d_in[1];
    const float* bias     = (const float*)d_in[2];
    const int*   b_from_a = (const int*)d_in[3];
    const int*   a_from_b = (const int*)d_in[4];
    float*       out      = (float*)d_out;

    const int M = in_sizes[0] / DD;   // 50000

    dim3 ggrid(DD / BN, (M + BM - 1) / BM);   // (4, 391): same-x blocks adjacent
    gemm_kernel<<<ggrid, 256>>>(x, W, bias, M);

    const int ablocks = (M + 3) / 4;
    agg_kernel<<<ablocks, 256>>>(b_from_a, a_from_b, out, M);
}

// round 5
// speedup vs baseline: 1.6422x; 1.2056x over previous
#include <cuda_runtime.h>
#include <cstdint>

#define MAX_ATOMS 50000
#define DD 256
#define NB 16

#define BM 128
#define BN 64
#define BK 16
#define NCH (DD / BK)     // 16 K-chunks
#define STG 3             // cp.async pipeline stages
#define RW 20             // smem words per row (16 data + 4 pad; conflict-free)

// Scratch: h = x@W.T+b (row 0 zeroed), and tf32-rounded W.
__device__ float g_h[(size_t)MAX_ATOMS * DD];
__device__ float g_Wr[DD * DD];

// ---------------------------------------------------------------------------
// helpers (sm_80-baseline features only — harness builds plain sm_103 PTX)
// ---------------------------------------------------------------------------
__device__ __forceinline__ uint32_t smem_u32(const void* p) {
    uint32_t a;
    asm("{ .reg .u64 t; cvta.to.shared.u64 t, %1; cvt.u32.u64 %0, t; }" : "=r"(a) : "l"(p));
    return a;
}
__device__ __forceinline__ uint32_t f2tf32(float f) {
    uint32_t u; asm("cvt.rna.tf32.f32 %0, %1;" : "=r"(u) : "f"(f)); return u;
}
__device__ __forceinline__ void ldsm4(uint32_t r[4], uint32_t a) {
    asm volatile("ldmatrix.sync.aligned.m8n8.x4.shared.b16 {%0,%1,%2,%3}, [%4];"
                 : "=r"(r[0]), "=r"(r[1]), "=r"(r[2]), "=r"(r[3]) : "r"(a));
}
__device__ __forceinline__ void cp16(uint32_t dst, const void* src, uint32_t nbytes) {
    asm volatile("cp.async.cg.shared.global [%0], [%1], 16, %2;"
                 :: "r"(dst), "l"(src), "r"(nbytes));
}
__device__ __forceinline__ void mma_tf32(float d[4], const uint32_t a[4],
                                         uint32_t b0, uint32_t b1) {
    asm volatile(
        "mma.sync.aligned.m16n8k8.row.col.f32.tf32.tf32.f32 "
        "{%0,%1,%2,%3}, {%4,%5,%6,%7}, {%8,%9}, {%0,%1,%2,%3};"
        : "+f"(d[0]), "+f"(d[1]), "+f"(d[2]), "+f"(d[3])
        : "r"(a[0]), "r"(a[1]), "r"(a[2]), "r"(a[3]), "r"(b0), "r"(b1));
}

// ---------------------------------------------------------------------------
// Kernel 0: round W to tf32 (rna) once -> g_Wr. 65536 elems, ~2us.
// ---------------------------------------------------------------------------
__global__ __launch_bounds__(256) void wconv_kernel(const float* __restrict__ W) {
    const int i = blockIdx.x * 256 + threadIdx.x;
    ((uint32_t*)g_Wr)[i] = f2tf32(W[i]);
}

// ---------------------------------------------------------------------------
// Kernel 1: h = x @ W.T + b (row 0 zeroed).
// 256 threads = 8 warps (4x2), tile 128x64, warp tile 32x32.
// cp.async 3-stage pipeline + ldmatrix fragment loads.
// ---------------------------------------------------------------------------
__global__ __launch_bounds__(256) void gemm_kernel(
    const float* __restrict__ x, const float* __restrict__ bias, int M)
{
    __shared__ uint32_t sA[STG][BM][RW];
    __shared__ uint32_t sB[STG][BN][RW];

    const int tid  = threadIdx.x;
    const int bn   = blockIdx.x * BN;   // N tiles adjacent -> x shared via L2
    const int bm   = blockIdx.y * BM;
    const int warp = tid >> 5, lane = tid & 31;
    const int wr   = (warp >> 1) * 32, wc = (warp & 1) * 32;
    const int g    = lane >> 2,  tg = lane & 3;
    const int sel  = lane >> 3,  r8 = lane & 7;

    const uint32_t sAu = smem_u32(sA), sBu = smem_u32(sB);

    // cp.async mapping: thread t -> row t/4, 16B chunk t%4. A: 2 rows/thread.
    const int crow = tid >> 2;          // 0..63
    const int ckc  = tid & 3;
    const float* xsrc0 = x     + (size_t)(bm + crow)      * DD + ckc * 4;
    const float* xsrc1 = x     + (size_t)(bm + crow + 64) * DD + ckc * 4;
    const float* wsrc  = g_Wr  + (size_t)(bn + crow)      * DD + ckc * 4;
    const uint32_t nb0 = (bm + crow      < M) ? 16u : 0u;   // zfill OOB rows
    const uint32_t nb1 = (bm + crow + 64 < M) ? 16u : 0u;
    const uint32_t dA0 = sAu + (uint32_t)((crow       * RW + ckc * 4) * 4);
    const uint32_t dA1 = sAu + (uint32_t)(((crow + 64) * RW + ckc * 4) * 4);
    const uint32_t dB  = sBu + (uint32_t)((crow       * RW + ckc * 4) * 4);

    // ldmatrix per-lane base addresses (x4 = four 8-row x 16B tiles)
    uint32_t aBase[2], bBase[2];
    #pragma unroll
    for (int mi = 0; mi < 2; mi++) {
        const int row = wr + mi * 16 + (sel & 1) * 8 + r8;   // a0/a1 rows, a2/a3 k+4
        aBase[mi] = sAu + (uint32_t)((row * RW + (sel >> 1) * 4) * 4);
    }
    #pragma unroll
    for (int p = 0; p < 2; p++) {
        const int row = wc + p * 16 + (sel >> 1) * 8 + r8;   // b tiles: n lo/hi, k lo/hi
        bBase[p] = sBu + (uint32_t)((row * RW + (sel & 1) * 4) * 4);
    }

    float acc[2][4][4];
    #pragma unroll
    for (int mi = 0; mi < 2; mi++)
        #pragma unroll
        for (int ni = 0; ni < 4; ni++)
            #pragma unroll
            for (int e = 0; e < 4; e++) acc[mi][ni][e] = 0.f;

    auto issue = [&](int c, int s) {
        const uint32_t ao = (uint32_t)(s * BM * RW * 4);
        const uint32_t bo = (uint32_t)(s * BN * RW * 4);
        const int ko = c * BK;
        cp16(dA0 + ao, xsrc0 + ko, nb0);
        cp16(dA1 + ao, xsrc1 + ko, nb1);
        cp16(dB  + bo, wsrc  + ko, 16u);
    };

    issue(0, 0); asm volatile("cp.async.commit_group;" ::: "memory");
    issue(1, 1); asm volatile("cp.async.commit_group;" ::: "memory");

    #pragma unroll
    for (int c = 0; c < NCH; c++) {
        const int s = c % STG;
        asm volatile("cp.async.wait_group 1;" ::: "memory");
        __syncthreads();
        if (c + 2 < NCH) issue(c + 2, (c + 2) % STG);   // stage (c-1)%3, safe post-sync
        asm volatile("cp.async.commit_group;" ::: "memory");

        const uint32_t ao = (uint32_t)(s * BM * RW * 4);
        const uint32_t bo = (uint32_t)(s * BN * RW * 4);
        #pragma unroll
        for (int kk = 0; kk < BK; kk += 8) {
            uint32_t af[2][4], bf[2][4];
            ldsm4(af[0], aBase[0] + ao + kk * 4);
            ldsm4(af[1], aBase[1] + ao + kk * 4);
            ldsm4(bf[0], bBase[0] + bo + kk * 4);
            ldsm4(bf[1], bBase[1] + bo + kk * 4);
            #pragma unroll
            for (int mi = 0; mi < 2; mi++) {
                #pragma unroll
                for (int p = 0; p < 2; p++) {
                    mma_tf32(acc[mi][p * 2 + 0], af[mi], bf[p][0], bf[p][1]);
                    mma_tf32(acc[mi][p * 2 + 1], af[mi], bf[p][2], bf[p][3]);
                }
            }
        }
    }

    // epilogue: + bias, zero row 0, store
    #pragma unroll
    for (int mi = 0; mi < 2; mi++) {
        #pragma unroll
        for (int ni = 0; ni < 4; ni++) {
            const int col = bn + wc + ni * 8 + tg * 2;
            const float b0 = bias[col];
            const float b1 = bias[col + 1];
            const int r0 = bm + wr + mi * 16 + g;
            const int r1 = r0 + 8;
            if (r0 < M) {
                const float v0 = (r0 == 0) ? 0.f : acc[mi][ni][0] + b0;
                const float v1 = (r0 == 0) ? 0.f : acc[mi][ni][1] + b1;
                g_h[(size_t)r0 * DD + col]     = v0;
                g_h[(size_t)r0 * DD + col + 1] = v1;
            }
            if (r1 < M) {
                g_h[(size_t)r1 * DD + col]     = acc[mi][ni][2] + b0;
                g_h[(size_t)r1 * DD + col + 1] = acc[mi][ni][3] + b1;
            }
        }
    }
}

// ---------------------------------------------------------------------------
// Kernel 2: out[i] = relu(h[i] + sum_k h[b_from_a[a_from_b[i][k]]])
// (unchanged — measured at its L2/latency floor)
// ---------------------------------------------------------------------------
__global__ __launch_bounds__(256) void agg_kernel(
    const int* __restrict__ b_from_a, const int* __restrict__ a_from_b,
    float* __restrict__ out, int M)
{
    const int atom = blockIdx.x * 4 + (threadIdx.x >> 6);
    if (atom >= M) return;
    const int t = threadIdx.x & 63;

    int idx[NB];
    #pragma unroll
    for (int k = 0; k < NB; k++) idx[k] = __ldg(a_from_b + (size_t)atom * NB + k);
    #pragma unroll
    for (int k = 0; k < NB; k++) idx[k] = __ldg(b_from_a + idx[k]);

    const float4* h4 = (const float4*)g_h;
    float4 acc = h4[(size_t)atom * (DD / 4) + t];

    #pragma unroll
    for (int k = 0; k < NB; k++) {
        float4 v = __ldg(h4 + (size_t)idx[k] * (DD / 4) + t);
        acc.x += v.x; acc.y += v.y; acc.z += v.z; acc.w += v.w;
    }

    acc.x = fmaxf(acc.x, 0.f);
    acc.y = fmaxf(acc.y, 0.f);
    acc.z = fmaxf(acc.z, 0.f);
    acc.w = fmaxf(acc.w, 0.f);
    ((float4*)out)[(size_t)atom * (DD / 4) + t] = acc;
}

// ---------------------------------------------------------------------------
// Launch: inputs per metadata order: x, W, b, b_from_a, a_from_b
// ---------------------------------------------------------------------------
extern "C" void kernel_launch(void* const* d_in, const int* in_sizes, int n_in,
                              void* d_out, int out_size) {
    const float* x        = (const float*)d_in[0];
    const float* W        = (const float*)d_in[1];
    const float* bias     = (const float*)d_in[2];
    const int*   b_from_a = (const int*)d_in[3];
    const int*   a_from_b = (const int*)d_in[4];
    float*       out      = (float*)d_out;

    const int M = in_sizes[0] / DD;   // 50000

    wconv_kernel<<<DD * DD / 256, 256>>>(W);

    dim3 ggrid(DD / BN, (M + BM - 1) / BM);   // (4, 391)
    gemm_kernel<<<ggrid, 256>>>(x, bias, M);

    agg_kernel<<<(M + 3) / 4, 256>>>(b_from_a, a_from_b, out, M);
}